// round 3
// baseline (speedup 1.0000x reference)
#include <cuda_runtime.h>
#include <cuda_bf16.h>
#include <cstdint>

// Problem constants (fixed by dataset): N=100000, D=64, E=1600000
#define NMAX 100000
#define EMAX 1600000
#define F    192          // 3*D features per hop stage
#define OUTC 576          // 9*64 output columns per node

// ---- scratch (static device globals; no runtime allocation allowed) ----
__device__ float g_y1[(size_t)NMAX * F];     // hop-1 result (degrev * spmm(x3))
__device__ float g_y2[(size_t)NMAX * F];     // hop-2 result
__device__ float2 g_s2[NMAX];                // (rsqrt(deg), sqrt(deg)) per node
__device__ int   g_rowptr[NMAX + 1];
__device__ int   g_cursor[NMAX];             // doubles as counts then fill cursor
__device__ int   g_ecol[EMAX];               // CSR column indices

// ---------------------------------------------------------------------------
// K1: zero counts + precompute per-node scale factors
// ---------------------------------------------------------------------------
__global__ void init_kernel(const float* __restrict__ deg, int N) {
    int i = blockIdx.x * blockDim.x + threadIdx.x;
    if (i < N) {
        g_cursor[i] = 0;
        float d = deg[i];
        float r = rsqrtf(d);
        g_s2[i] = make_float2(r, d * r);   // (deg^-1/2, deg^1/2)
    }
}

// ---------------------------------------------------------------------------
// K2: histogram of destination rows
// ---------------------------------------------------------------------------
__global__ void hist_kernel(const int* __restrict__ row, int E) {
    int e = blockIdx.x * blockDim.x + threadIdx.x;
    if (e < E) atomicAdd(&g_cursor[row[e]], 1);
}

// ---------------------------------------------------------------------------
// K3: single-block exclusive scan (4 elems/thread, 1024 threads, carry loop)
//     counts are in g_cursor; writes rowptr[i] and resets g_cursor[i]=rowptr[i]
// ---------------------------------------------------------------------------
__global__ void scan_kernel(int N) {
    __shared__ int warp_sums[32];
    __shared__ int s_carry;
    const int tid = threadIdx.x, lane = tid & 31, wid = tid >> 5;
    if (tid == 0) s_carry = 0;
    __syncthreads();

    for (int base = 0; base < N; base += 4096) {
        int idx = base + tid * 4;
        int v0 = (idx     < N) ? g_cursor[idx]     : 0;
        int v1 = (idx + 1 < N) ? g_cursor[idx + 1] : 0;
        int v2 = (idx + 2 < N) ? g_cursor[idx + 2] : 0;
        int v3 = (idx + 3 < N) ? g_cursor[idx + 3] : 0;
        int t = v0 + v1 + v2 + v3;

        // inclusive warp scan of t
        int s = t;
        #pragma unroll
        for (int off = 1; off < 32; off <<= 1) {
            int u = __shfl_up_sync(0xFFFFFFFFu, s, off);
            if (lane >= off) s += u;
        }
        if (lane == 31) warp_sums[wid] = s;
        __syncthreads();
        if (wid == 0) {
            int ws = warp_sums[lane];
            int s2 = ws;
            #pragma unroll
            for (int off = 1; off < 32; off <<= 1) {
                int u = __shfl_up_sync(0xFFFFFFFFu, s2, off);
                if (lane >= off) s2 += u;
            }
            warp_sums[lane] = s2 - ws;   // exclusive warp prefix
        }
        __syncthreads();
        int carry = s_carry;
        int excl  = carry + warp_sums[wid] + (s - t);

        int e1 = excl + v0, e2 = e1 + v1, e3 = e2 + v2;
        if (idx     < N) { g_rowptr[idx]     = excl; g_cursor[idx]     = excl; }
        if (idx + 1 < N) { g_rowptr[idx + 1] = e1;   g_cursor[idx + 1] = e1;   }
        if (idx + 2 < N) { g_rowptr[idx + 2] = e2;   g_cursor[idx + 2] = e2;   }
        if (idx + 3 < N) { g_rowptr[idx + 3] = e3;   g_cursor[idx + 3] = e3;   }
        __syncthreads();                 // everyone has read s_carry
        if (tid == 1023) s_carry = e3 + v3;   // chunk total (OOB v's are 0)
        __syncthreads();
    }
    if (tid == 0) g_rowptr[N] = s_carry;
}

// ---------------------------------------------------------------------------
// K4: scatter edges into CSR buckets
// ---------------------------------------------------------------------------
__global__ void fill_kernel(const int* __restrict__ row, const int* __restrict__ col, int E) {
    int e = blockIdx.x * blockDim.x + threadIdx.x;
    if (e < E) {
        int p = atomicAdd(&g_cursor[row[e]], 1);
        g_ecol[p] = col[e];
    }
}

// ---------------------------------------------------------------------------
// K5: hop-1 SpMM. y1[i] = (1/deg[i]) * sum_j x3[j], with x3[j] expanded on the
//     fly from x[j] (256B gather) and per-node scalars (8B gather).
//     One warp per destination node; thread l owns float2 columns l, l+32, l+64.
// ---------------------------------------------------------------------------
__global__ void spmm1_kernel(const float* __restrict__ x,
                             const float* __restrict__ deg, int N) {
    int w = (blockIdx.x * blockDim.x + threadIdx.x) >> 5;
    int lane = threadIdx.x & 31;
    if (w >= N) return;
    int s = g_rowptr[w], e = g_rowptr[w + 1];

    float a0x = 0.f, a0y = 0.f, a1x = 0.f, a1y = 0.f, a2x = 0.f, a2y = 0.f;
    for (int p = s; p < e; p++) {
        int j = __ldg(&g_ecol[p]);
        float2 xv = __ldg(((const float2*)(x + (size_t)j * 64)) + lane);
        float2 sc = __ldg(&g_s2[j]);          // (rsqrt, sqrt) — broadcast-ish
        a0x += xv.x;          a0y += xv.y;
        a1x += xv.x * sc.x;   a1y += xv.y * sc.x;
        a2x += xv.x * sc.y;   a2y += xv.y * sc.y;
    }
    float dr = 1.0f / deg[w];
    float2* out = (float2*)(g_y1 + (size_t)w * F);
    out[lane]      = make_float2(a0x * dr, a0y * dr);
    out[lane + 32] = make_float2(a1x * dr, a1y * dr);
    out[lane + 64] = make_float2(a2x * dr, a2y * dr);
}

// ---------------------------------------------------------------------------
// K6: hop-2 SpMM. y2[i] = (1/deg[i]) * sum_j y1[j]  -  x3[i] (on the fly)
// ---------------------------------------------------------------------------
__global__ void spmm2_kernel(const float* __restrict__ x,
                             const float* __restrict__ deg, int N) {
    int w = (blockIdx.x * blockDim.x + threadIdx.x) >> 5;
    int lane = threadIdx.x & 31;
    if (w >= N) return;
    int s = g_rowptr[w], e = g_rowptr[w + 1];

    float a0x = 0.f, a0y = 0.f, a1x = 0.f, a1y = 0.f, a2x = 0.f, a2y = 0.f;
    for (int p = s; p < e; p++) {
        int j = __ldg(&g_ecol[p]);
        const float2* r = (const float2*)(g_y1 + (size_t)j * F);
        float2 v0 = __ldg(r + lane);
        float2 v1 = __ldg(r + lane + 32);
        float2 v2 = __ldg(r + lane + 64);
        a0x += v0.x; a0y += v0.y;
        a1x += v1.x; a1y += v1.y;
        a2x += v2.x; a2y += v2.y;
    }
    float dr = 1.0f / deg[w];
    float2 sc = g_s2[w];
    float2 xv = __ldg(((const float2*)(x + (size_t)w * 64)) + lane);
    float2* out = (float2*)(g_y2 + (size_t)w * F);
    out[lane]      = make_float2(a0x * dr - xv.x,        a0y * dr - xv.y);
    out[lane + 32] = make_float2(a1x * dr - xv.x * sc.x, a1y * dr - xv.y * sc.x);
    out[lane + 64] = make_float2(a2x * dr - xv.x * sc.y, a2y * dr - xv.y * sc.y);
}

// ---------------------------------------------------------------------------
// K7: transposed output. out[n, d*9+k] = concat(x3|y1|y2)[n, k*64+d].
//     4 nodes per 256-thread block; smem tile padded (stride 65) for
//     conflict-free transpose; global loads and stores fully coalesced.
// ---------------------------------------------------------------------------
__global__ void output_kernel(const float* __restrict__ x, float* __restrict__ out, int N) {
    __shared__ float tile[4 * 9 * 65];        // [q][k*65 + d]
    int nbase = blockIdx.x * 4;
    int tid = threadIdx.x;

    // load phase: 4*576 concat values, coalesced
    for (int t = tid; t < 4 * OUTC; t += 256) {
        int q = t / OUTC, c = t - q * OUTC;
        int n = nbase + q;
        float v = 0.f;
        if (n < N) {
            if (c < F) {                       // x3 block, computed on the fly
                int b = c >> 6, d = c & 63;
                float f = 1.0f;
                if (b) { float2 sc = g_s2[n]; f = (b == 1) ? sc.x : sc.y; }
                v = __ldg(&x[(size_t)n * 64 + d]) * f;
            } else if (c < 2 * F) {
                v = g_y1[(size_t)n * F + (c - F)];
            } else {
                v = g_y2[(size_t)n * F + (c - 2 * F)];
            }
        }
        int k = c >> 6, d = c & 63;
        tile[q * 585 + k * 65 + d] = v;
    }
    __syncthreads();

    // store phase: contiguous global writes
    for (int t = tid; t < 4 * OUTC; t += 256) {
        int q = t / OUTC, r = t - q * OUTC;
        int n = nbase + q;
        if (n < N) {
            int d = r / 9, k = r - d * 9;
            out[(size_t)n * OUTC + r] = tile[q * 585 + k * 65 + d];
        }
    }
}

// ---------------------------------------------------------------------------
extern "C" void kernel_launch(void* const* d_in, const int* in_sizes, int n_in,
                              void* d_out, int out_size) {
    const float* x   = (const float*)d_in[0];
    const float* deg = (const float*)d_in[1];
    const int*   row = (const int*)d_in[2];
    const int*   col = (const int*)d_in[3];
    float* out = (float*)d_out;

    int N = in_sizes[1];          // deg has N elements
    int E = in_sizes[2];          // row has E elements

    init_kernel<<<(N + 255) / 256, 256>>>(deg, N);
    hist_kernel<<<(E + 255) / 256, 256>>>(row, E);
    scan_kernel<<<1, 1024>>>(N);
    fill_kernel<<<(E + 255) / 256, 256>>>(row, col, E);
    spmm1_kernel<<<((size_t)N * 32 + 255) / 256, 256>>>(x, deg, N);
    spmm2_kernel<<<((size_t)N * 32 + 255) / 256, 256>>>(x, deg, N);
    output_kernel<<<(N + 3) / 4, 256>>>(x, out, N);
}

// round 4
// speedup vs baseline: 1.0024x; 1.0024x over previous
#include <cuda_runtime.h>
#include <cuda_bf16.h>
#include <cstdint>

// Problem constants (fixed by dataset): N=100000, D=64, E=1600000
#define NMAX 100000
#define EMAX 1600000
#define ESLOTS (EMAX + NMAX)   // rowptr built from deg upper-bounds counts
#define F    192               // 3*D features per hop stage
#define OUTC 576               // 9*64 output columns per node

// ---- scratch (static device globals; no runtime allocation allowed) ----
__device__ float g_y1[(size_t)NMAX * F];     // hop-1 result (degrev * spmm(x3))
__device__ float2 g_s2[NMAX];                // (rsqrt(deg), sqrt(deg)) per node
__device__ int   g_rowptr[NMAX + 1];
__device__ int   g_cursor[NMAX];             // fill cursor; after fill = row end
__device__ int   g_ecol[ESLOTS];             // CSR column indices

// ---------------------------------------------------------------------------
// K1: precompute per-node scale factors
// ---------------------------------------------------------------------------
__global__ void init_kernel(const float* __restrict__ deg, int N) {
    int i = blockIdx.x * blockDim.x + threadIdx.x;
    if (i < N) {
        float d = deg[i];
        float r = rsqrtf(d);
        g_s2[i] = make_float2(r, d * r);   // (deg^-1/2, deg^1/2)
    }
}

// ---------------------------------------------------------------------------
// K2: single-block exclusive scan over (int)deg (upper bound on row counts).
//     Writes rowptr[i] and initializes the fill cursor g_cursor[i]=rowptr[i].
//     After fill_kernel, g_cursor[i] is the true end of row i.
// ---------------------------------------------------------------------------
__global__ void scan_kernel(const float* __restrict__ deg, int N) {
    __shared__ int warp_sums[32];
    __shared__ int s_carry;
    const int tid = threadIdx.x, lane = tid & 31, wid = tid >> 5;
    if (tid == 0) s_carry = 0;
    __syncthreads();

    for (int base = 0; base < N; base += 4096) {
        int idx = base + tid * 4;
        int v0 = (idx     < N) ? (int)deg[idx]     : 0;
        int v1 = (idx + 1 < N) ? (int)deg[idx + 1] : 0;
        int v2 = (idx + 2 < N) ? (int)deg[idx + 2] : 0;
        int v3 = (idx + 3 < N) ? (int)deg[idx + 3] : 0;
        int t = v0 + v1 + v2 + v3;

        // inclusive warp scan of t
        int s = t;
        #pragma unroll
        for (int off = 1; off < 32; off <<= 1) {
            int u = __shfl_up_sync(0xFFFFFFFFu, s, off);
            if (lane >= off) s += u;
        }
        if (lane == 31) warp_sums[wid] = s;
        __syncthreads();
        if (wid == 0) {
            int ws = warp_sums[lane];
            int s2 = ws;
            #pragma unroll
            for (int off = 1; off < 32; off <<= 1) {
                int u = __shfl_up_sync(0xFFFFFFFFu, s2, off);
                if (lane >= off) s2 += u;
            }
            warp_sums[lane] = s2 - ws;   // exclusive warp prefix
        }
        __syncthreads();
        int carry = s_carry;
        int excl  = carry + warp_sums[wid] + (s - t);

        int e1 = excl + v0, e2 = e1 + v1, e3 = e2 + v2;
        if (idx     < N) { g_rowptr[idx]     = excl; g_cursor[idx]     = excl; }
        if (idx + 1 < N) { g_rowptr[idx + 1] = e1;   g_cursor[idx + 1] = e1;   }
        if (idx + 2 < N) { g_rowptr[idx + 2] = e2;   g_cursor[idx + 2] = e2;   }
        if (idx + 3 < N) { g_rowptr[idx + 3] = e3;   g_cursor[idx + 3] = e3;   }
        __syncthreads();                 // everyone has read s_carry
        if (tid == 1023) s_carry = e3 + v3;   // chunk total (OOB v's are 0)
        __syncthreads();
    }
    if (tid == 0) g_rowptr[N] = s_carry;
}

// ---------------------------------------------------------------------------
// K3: scatter edges into CSR buckets
// ---------------------------------------------------------------------------
__global__ void fill_kernel(const int* __restrict__ row, const int* __restrict__ col, int E) {
    int e = blockIdx.x * blockDim.x + threadIdx.x;
    if (e < E) {
        int p = atomicAdd(&g_cursor[row[e]], 1);
        g_ecol[p] = col[e];
    }
}

// ---------------------------------------------------------------------------
// K4: hop-1 SpMM. y1[i] = (1/deg[i]) * sum_j x3[j], with x3[j] expanded on the
//     fly from x[j] (256B gather) and per-node scalars (8B gather).
//     One warp per destination node; thread l owns float2 columns l, l+32, l+64.
// ---------------------------------------------------------------------------
__global__ void spmm1_kernel(const float* __restrict__ x,
                             const float* __restrict__ deg, int N) {
    int w = (blockIdx.x * blockDim.x + threadIdx.x) >> 5;
    int lane = threadIdx.x & 31;
    if (w >= N) return;
    int s = g_rowptr[w], e = g_cursor[w];   // true end after fill

    float a0x = 0.f, a0y = 0.f, a1x = 0.f, a1y = 0.f, a2x = 0.f, a2y = 0.f;
    #pragma unroll 2
    for (int p = s; p < e; p++) {
        int j = __ldg(&g_ecol[p]);
        float2 xv = __ldg(((const float2*)(x + (size_t)j * 64)) + lane);
        float2 sc = __ldg(&g_s2[j]);          // broadcast within warp
        a0x += xv.x;          a0y += xv.y;
        a1x += xv.x * sc.x;   a1y += xv.y * sc.x;
        a2x += xv.x * sc.y;   a2y += xv.y * sc.y;
    }
    float dr = 1.0f / deg[w];
    float2* out = (float2*)(g_y1 + (size_t)w * F);
    out[lane]      = make_float2(a0x * dr, a0y * dr);
    out[lane + 32] = make_float2(a1x * dr, a1y * dr);
    out[lane + 64] = make_float2(a2x * dr, a2y * dr);
}

// ---------------------------------------------------------------------------
// K5: FUSED hop-2 SpMM + transposed output.
//     One warp per node: gather y1 over neighbors, compute
//     y2 = degrev*sum - x3 in registers, then emit all 576 output columns
//     out[n, d*9+k] = concat(x3|y1|y2)[n, k*64+d] through a per-warp smem
//     tile (stride-65 padded). y2 never touches global scratch.
// ---------------------------------------------------------------------------
__global__ void spmm2_out_kernel(const float* __restrict__ x,
                                 const float* __restrict__ deg,
                                 float* __restrict__ out, int N) {
    __shared__ float tile[8 * 9 * 65];        // per-warp 585-float tile
    int wid = threadIdx.x >> 5, lane = threadIdx.x & 31;
    int n = blockIdx.x * 8 + wid;
    if (n >= N) return;
    float* t = tile + wid * 585;

    int s = g_rowptr[n], e = g_cursor[n];
    float a0x = 0.f, a0y = 0.f, a1x = 0.f, a1y = 0.f, a2x = 0.f, a2y = 0.f;
    #pragma unroll 2
    for (int p = s; p < e; p++) {
        int j = __ldg(&g_ecol[p]);
        const float2* r = (const float2*)(g_y1 + (size_t)j * F);
        float2 v0 = __ldg(r + lane);
        float2 v1 = __ldg(r + lane + 32);
        float2 v2 = __ldg(r + lane + 64);
        a0x += v0.x; a0y += v0.y;
        a1x += v1.x; a1y += v1.y;
        a2x += v2.x; a2y += v2.y;
    }

    float dr = 1.0f / deg[n];
    float2 sc = g_s2[n];
    float2 xv = __ldg(((const float2*)(x + (size_t)n * 64)) + lane);
    const float2* yr = (const float2*)(g_y1 + (size_t)n * F);
    float2 y0 = yr[lane], y1v = yr[lane + 32], y2v = yr[lane + 64];

    int d0 = lane * 2;
    // k = 0..2 : x3 blocks (x, x*rsqrt(deg), x*sqrt(deg))
    t[0 * 65 + d0] = xv.x;          t[0 * 65 + d0 + 1] = xv.y;
    t[1 * 65 + d0] = xv.x * sc.x;   t[1 * 65 + d0 + 1] = xv.y * sc.x;
    t[2 * 65 + d0] = xv.x * sc.y;   t[2 * 65 + d0 + 1] = xv.y * sc.y;
    // k = 3..5 : y1 blocks
    t[3 * 65 + d0] = y0.x;          t[3 * 65 + d0 + 1] = y0.y;
    t[4 * 65 + d0] = y1v.x;         t[4 * 65 + d0 + 1] = y1v.y;
    t[5 * 65 + d0] = y2v.x;         t[5 * 65 + d0 + 1] = y2v.y;
    // k = 6..8 : y2 = degrev*spmm(y1) - x3
    t[6 * 65 + d0] = a0x * dr - xv.x;          t[6 * 65 + d0 + 1] = a0y * dr - xv.y;
    t[7 * 65 + d0] = a1x * dr - xv.x * sc.x;   t[7 * 65 + d0 + 1] = a1y * dr - xv.y * sc.x;
    t[8 * 65 + d0] = a2x * dr - xv.x * sc.y;   t[8 * 65 + d0 + 1] = a2y * dr - xv.y * sc.y;
    __syncwarp();

    // coalesced store of the transposed row: out[n, d*9+k]
    float* o = out + (size_t)n * OUTC;
    #pragma unroll
    for (int i = 0; i < 18; i++) {
        int r = i * 32 + lane;
        int d = r / 9, k = r - d * 9;
        o[r] = t[k * 65 + d];
    }
}

// ---------------------------------------------------------------------------
extern "C" void kernel_launch(void* const* d_in, const int* in_sizes, int n_in,
                              void* d_out, int out_size) {
    const float* x   = (const float*)d_in[0];
    const float* deg = (const float*)d_in[1];
    const int*   row = (const int*)d_in[2];
    const int*   col = (const int*)d_in[3];
    float* out = (float*)d_out;

    int N = in_sizes[1];          // deg has N elements
    int E = in_sizes[2];          // row has E elements

    init_kernel<<<(N + 255) / 256, 256>>>(deg, N);
    scan_kernel<<<1, 1024>>>(deg, N);
    fill_kernel<<<(E + 255) / 256, 256>>>(row, col, E);
    spmm1_kernel<<<((size_t)N * 32 + 255) / 256, 256>>>(x, deg, N);
    spmm2_out_kernel<<<(N + 7) / 8, 256>>>(x, deg, out, N);
}

// round 5
// speedup vs baseline: 1.5380x; 1.5344x over previous
#include <cuda_runtime.h>
#include <cuda_bf16.h>
#include <cuda_fp16.h>
#include <cstdint>

// Problem constants (fixed by dataset): N=100000, D=64, E=1600000
#define NMAX 100000
#define EMAX 1600000
#define ESLOTS (EMAX + NMAX)   // rowptr built from deg upper-bounds counts
#define F    192               // 3*D features per hop stage
#define OUTC 576               // 9*64 output columns per node

// ---- scratch (static device globals; no runtime allocation allowed) ----
__device__ float  g_y1 [(size_t)NMAX * F];   // hop-1 result, fp32 (exact output copy)
__device__ __half g_y1h[(size_t)NMAX * F];   // hop-1 result, fp16 (for hop-2 gather)
__device__ float2 g_s2[NMAX];                // (rsqrt(deg), sqrt(deg)) per node
__device__ int   g_rowptr[NMAX + 1];
__device__ int   g_cursor[NMAX];             // fill cursor; after fill = row end
__device__ int   g_ecol[ESLOTS];             // CSR column indices

// ---------------------------------------------------------------------------
// K1: precompute per-node scale factors
// ---------------------------------------------------------------------------
__global__ void init_kernel(const float* __restrict__ deg, int N) {
    int i = blockIdx.x * blockDim.x + threadIdx.x;
    if (i < N) {
        float d = deg[i];
        float r = rsqrtf(d);
        g_s2[i] = make_float2(r, d * r);   // (deg^-1/2, deg^1/2)
    }
}

// ---------------------------------------------------------------------------
// K2: single-block exclusive scan over (int)deg (upper bound on row counts).
// ---------------------------------------------------------------------------
__global__ void scan_kernel(const float* __restrict__ deg, int N) {
    __shared__ int warp_sums[32];
    __shared__ int s_carry;
    const int tid = threadIdx.x, lane = tid & 31, wid = tid >> 5;
    if (tid == 0) s_carry = 0;
    __syncthreads();

    for (int base = 0; base < N; base += 4096) {
        int idx = base + tid * 4;
        int v0 = (idx     < N) ? (int)deg[idx]     : 0;
        int v1 = (idx + 1 < N) ? (int)deg[idx + 1] : 0;
        int v2 = (idx + 2 < N) ? (int)deg[idx + 2] : 0;
        int v3 = (idx + 3 < N) ? (int)deg[idx + 3] : 0;
        int t = v0 + v1 + v2 + v3;

        int s = t;
        #pragma unroll
        for (int off = 1; off < 32; off <<= 1) {
            int u = __shfl_up_sync(0xFFFFFFFFu, s, off);
            if (lane >= off) s += u;
        }
        if (lane == 31) warp_sums[wid] = s;
        __syncthreads();
        if (wid == 0) {
            int ws = warp_sums[lane];
            int s2 = ws;
            #pragma unroll
            for (int off = 1; off < 32; off <<= 1) {
                int u = __shfl_up_sync(0xFFFFFFFFu, s2, off);
                if (lane >= off) s2 += u;
            }
            warp_sums[lane] = s2 - ws;
        }
        __syncthreads();
        int carry = s_carry;
        int excl  = carry + warp_sums[wid] + (s - t);

        int e1 = excl + v0, e2 = e1 + v1, e3 = e2 + v2;
        if (idx     < N) { g_rowptr[idx]     = excl; g_cursor[idx]     = excl; }
        if (idx + 1 < N) { g_rowptr[idx + 1] = e1;   g_cursor[idx + 1] = e1;   }
        if (idx + 2 < N) { g_rowptr[idx + 2] = e2;   g_cursor[idx + 2] = e2;   }
        if (idx + 3 < N) { g_rowptr[idx + 3] = e3;   g_cursor[idx + 3] = e3;   }
        __syncthreads();
        if (tid == 1023) s_carry = e3 + v3;
        __syncthreads();
    }
    if (tid == 0) g_rowptr[N] = s_carry;
}

// ---------------------------------------------------------------------------
// K3: scatter edges into CSR buckets
// ---------------------------------------------------------------------------
__global__ void fill_kernel(const int* __restrict__ row, const int* __restrict__ col, int E) {
    int e = blockIdx.x * blockDim.x + threadIdx.x;
    if (e < E) {
        int p = atomicAdd(&g_cursor[row[e]], 1);
        g_ecol[p] = col[e];
    }
}

// ---------------------------------------------------------------------------
// K4: hop-1 SpMM. Writes y1 in fp32 (exact, for direct output) AND fp16
//     (for the hop-2 gather). One warp per destination node.
// ---------------------------------------------------------------------------
__global__ void spmm1_kernel(const float* __restrict__ x,
                             const float* __restrict__ deg, int N) {
    int w = (blockIdx.x * blockDim.x + threadIdx.x) >> 5;
    int lane = threadIdx.x & 31;
    if (w >= N) return;
    int s = g_rowptr[w], e = g_cursor[w];   // true end after fill

    float a0x = 0.f, a0y = 0.f, a1x = 0.f, a1y = 0.f, a2x = 0.f, a2y = 0.f;
    #pragma unroll 2
    for (int p = s; p < e; p++) {
        int j = __ldg(&g_ecol[p]);
        float2 xv = __ldg(((const float2*)(x + (size_t)j * 64)) + lane);
        float2 sc = __ldg(&g_s2[j]);          // broadcast within warp
        a0x += xv.x;          a0y += xv.y;
        a1x += xv.x * sc.x;   a1y += xv.y * sc.x;
        a2x += xv.x * sc.y;   a2y += xv.y * sc.y;
    }
    float dr = 1.0f / deg[w];
    a0x *= dr; a0y *= dr; a1x *= dr; a1y *= dr; a2x *= dr; a2y *= dr;

    float2* out = (float2*)(g_y1 + (size_t)w * F);
    out[lane]      = make_float2(a0x, a0y);
    out[lane + 32] = make_float2(a1x, a1y);
    out[lane + 64] = make_float2(a2x, a2y);

    __half2* outh = (__half2*)(g_y1h + (size_t)w * F);
    outh[lane]      = __floats2half2_rn(a0x, a0y);
    outh[lane + 32] = __floats2half2_rn(a1x, a1y);
    outh[lane + 64] = __floats2half2_rn(a2x, a2y);
}

// ---------------------------------------------------------------------------
// K5: FUSED hop-2 SpMM + transposed output. Gather uses the fp16 y1 copy
//     (halves bytes + L1tex wavefronts; 38.4MB working set is L2-resident).
//     Direct y1 output blocks read the fp32 copy (exact).
// ---------------------------------------------------------------------------
__global__ void spmm2_out_kernel(const float* __restrict__ x,
                                 const float* __restrict__ deg,
                                 float* __restrict__ out, int N) {
    __shared__ float tile[8 * 9 * 65];        // per-warp 585-float tile
    int wid = threadIdx.x >> 5, lane = threadIdx.x & 31;
    int n = blockIdx.x * 8 + wid;
    if (n >= N) return;
    float* t = tile + wid * 585;

    int s = g_rowptr[n], e = g_cursor[n];
    float a0x = 0.f, a0y = 0.f, a1x = 0.f, a1y = 0.f, a2x = 0.f, a2y = 0.f;
    #pragma unroll 4
    for (int p = s; p < e; p++) {
        int j = __ldg(&g_ecol[p]);
        const __half2* r = (const __half2*)(g_y1h + (size_t)j * F);
        float2 v0 = __half22float2(__ldg(r + lane));
        float2 v1 = __half22float2(__ldg(r + lane + 32));
        float2 v2 = __half22float2(__ldg(r + lane + 64));
        a0x += v0.x; a0y += v0.y;
        a1x += v1.x; a1y += v1.y;
        a2x += v2.x; a2y += v2.y;
    }

    float dr = 1.0f / deg[n];
    float2 sc = g_s2[n];
    float2 xv = __ldg(((const float2*)(x + (size_t)n * 64)) + lane);
    const float2* yr = (const float2*)(g_y1 + (size_t)n * F);
    float2 y0 = yr[lane], y1v = yr[lane + 32], y2v = yr[lane + 64];

    int d0 = lane * 2;
    // k = 0..2 : x3 blocks (x, x*rsqrt(deg), x*sqrt(deg))
    t[0 * 65 + d0] = xv.x;          t[0 * 65 + d0 + 1] = xv.y;
    t[1 * 65 + d0] = xv.x * sc.x;   t[1 * 65 + d0 + 1] = xv.y * sc.x;
    t[2 * 65 + d0] = xv.x * sc.y;   t[2 * 65 + d0 + 1] = xv.y * sc.y;
    // k = 3..5 : y1 blocks (fp32 copy, exact)
    t[3 * 65 + d0] = y0.x;          t[3 * 65 + d0 + 1] = y0.y;
    t[4 * 65 + d0] = y1v.x;         t[4 * 65 + d0 + 1] = y1v.y;
    t[5 * 65 + d0] = y2v.x;         t[5 * 65 + d0 + 1] = y2v.y;
    // k = 6..8 : y2 = degrev*spmm(y1) - x3
    t[6 * 65 + d0] = a0x * dr - xv.x;          t[6 * 65 + d0 + 1] = a0y * dr - xv.y;
    t[7 * 65 + d0] = a1x * dr - xv.x * sc.x;   t[7 * 65 + d0 + 1] = a1y * dr - xv.y * sc.x;
    t[8 * 65 + d0] = a2x * dr - xv.x * sc.y;   t[8 * 65 + d0 + 1] = a2y * dr - xv.y * sc.y;
    __syncwarp();

    // coalesced store of the transposed row: out[n, d*9+k]
    float* o = out + (size_t)n * OUTC;
    #pragma unroll
    for (int i = 0; i < 18; i++) {
        int r = i * 32 + lane;
        int d = r / 9, k = r - d * 9;
        o[r] = t[k * 65 + d];
    }
}

// ---------------------------------------------------------------------------
extern "C" void kernel_launch(void* const* d_in, const int* in_sizes, int n_in,
                              void* d_out, int out_size) {
    const float* x   = (const float*)d_in[0];
    const float* deg = (const float*)d_in[1];
    const int*   row = (const int*)d_in[2];
    const int*   col = (const int*)d_in[3];
    float* out = (float*)d_out;

    int N = in_sizes[1];          // deg has N elements
    int E = in_sizes[2];          // row has E elements

    init_kernel<<<(N + 255) / 256, 256>>>(deg, N);
    scan_kernel<<<1, 1024>>>(deg, N);
    fill_kernel<<<(E + 255) / 256, 256>>>(row, col, E);
    spmm1_kernel<<<((size_t)N * 32 + 255) / 256, 256>>>(x, deg, N);
    spmm2_out_kernel<<<(N + 7) / 8, 256>>>(x, deg, out, N);
}

// round 6
// speedup vs baseline: 1.6056x; 1.0440x over previous
#include <cuda_runtime.h>
#include <cuda_bf16.h>
#include <cuda_fp16.h>
#include <cstdint>

// Problem constants (fixed by dataset): N=100000, D=64, E=1600000
#define NMAX 100000
#define EMAX 1600000
#define ESLOTS (EMAX + NMAX)   // rowptr built from deg upper-bounds counts
#define F    192               // 3*D features per hop stage
#define OUTC 576               // 9*64 output columns per node

// ---- scratch (static device globals; no runtime allocation allowed) ----
__device__ __half g_xh [(size_t)NMAX * 64];  // x in fp16 (hop-1 gather)
__device__ __half g_y1h[(size_t)NMAX * F];   // hop-1 result, fp16
__device__ float2 g_s2[NMAX];                // (rsqrt(deg), sqrt(deg)) per node
__device__ int   g_rowptr[NMAX + 1];
__device__ int   g_cursor[NMAX];             // fill cursor; after fill = row end
__device__ int   g_ecol[ESLOTS];             // CSR column indices

// ---------------------------------------------------------------------------
// K1: per-node scale factors + x -> fp16 conversion (one pass)
//     grid covers N*32 threads; thread t converts float2 pair t of x.
// ---------------------------------------------------------------------------
__global__ void init_kernel(const float* __restrict__ x,
                            const float* __restrict__ deg, int N) {
    int t = blockIdx.x * blockDim.x + threadIdx.x;
    int total = N * 32;                 // N*64 floats as float2
    if (t < total) {
        float2 v = __ldg(((const float2*)x) + t);
        ((__half2*)g_xh)[t] = __floats2half2_rn(v.x, v.y);
    }
    if (t < N) {
        float d = __ldg(&deg[t]);
        float r = rsqrtf(d);
        g_s2[t] = make_float2(r, d * r);   // (deg^-1/2, deg^1/2)
    }
}

// ---------------------------------------------------------------------------
// K2: single-block exclusive scan over (int)deg (upper bound on row counts).
//     Writes rowptr[i] and fill cursor g_cursor[i]=rowptr[i]; after
//     fill_kernel, g_cursor[i] is the true end of row i.
// ---------------------------------------------------------------------------
__global__ void scan_kernel(const float* __restrict__ deg, int N) {
    __shared__ int warp_sums[32];
    __shared__ int s_carry;
    const int tid = threadIdx.x, lane = tid & 31, wid = tid >> 5;
    if (tid == 0) s_carry = 0;
    __syncthreads();

    for (int base = 0; base < N; base += 4096) {
        int idx = base + tid * 4;
        int v0 = (idx     < N) ? (int)deg[idx]     : 0;
        int v1 = (idx + 1 < N) ? (int)deg[idx + 1] : 0;
        int v2 = (idx + 2 < N) ? (int)deg[idx + 2] : 0;
        int v3 = (idx + 3 < N) ? (int)deg[idx + 3] : 0;
        int t = v0 + v1 + v2 + v3;

        int s = t;
        #pragma unroll
        for (int off = 1; off < 32; off <<= 1) {
            int u = __shfl_up_sync(0xFFFFFFFFu, s, off);
            if (lane >= off) s += u;
        }
        if (lane == 31) warp_sums[wid] = s;
        __syncthreads();
        if (wid == 0) {
            int ws = warp_sums[lane];
            int s2 = ws;
            #pragma unroll
            for (int off = 1; off < 32; off <<= 1) {
                int u = __shfl_up_sync(0xFFFFFFFFu, s2, off);
                if (lane >= off) s2 += u;
            }
            warp_sums[lane] = s2 - ws;
        }
        __syncthreads();
        int carry = s_carry;
        int excl  = carry + warp_sums[wid] + (s - t);

        int e1 = excl + v0, e2 = e1 + v1, e3 = e2 + v2;
        if (idx     < N) { g_rowptr[idx]     = excl; g_cursor[idx]     = excl; }
        if (idx + 1 < N) { g_rowptr[idx + 1] = e1;   g_cursor[idx + 1] = e1;   }
        if (idx + 2 < N) { g_rowptr[idx + 2] = e2;   g_cursor[idx + 2] = e2;   }
        if (idx + 3 < N) { g_rowptr[idx + 3] = e3;   g_cursor[idx + 3] = e3;   }
        __syncthreads();
        if (tid == 1023) s_carry = e3 + v3;
        __syncthreads();
    }
    if (tid == 0) g_rowptr[N] = s_carry;
}

// ---------------------------------------------------------------------------
// K3: scatter edges into CSR buckets
// ---------------------------------------------------------------------------
__global__ void fill_kernel(const int* __restrict__ row, const int* __restrict__ col, int E) {
    int e = blockIdx.x * blockDim.x + threadIdx.x;
    if (e < E) {
        int p = atomicAdd(&g_cursor[row[e]], 1);
        g_ecol[p] = col[e];
    }
}

// ---------------------------------------------------------------------------
// K4: hop-1 SpMM over fp16 x. y1[i] = (1/deg[i]) * sum_j x3[j], x3 expanded
//     on the fly (fp16 x gather = 128B/edge + 8B scalars). Warp per node.
// ---------------------------------------------------------------------------
__global__ void spmm1_kernel(const float* __restrict__ deg, int N) {
    int w = (blockIdx.x * blockDim.x + threadIdx.x) >> 5;
    int lane = threadIdx.x & 31;
    if (w >= N) return;
    int s = g_rowptr[w], e = g_cursor[w];   // true end after fill

    float a0x = 0.f, a0y = 0.f, a1x = 0.f, a1y = 0.f, a2x = 0.f, a2y = 0.f;
    #pragma unroll 4
    for (int p = s; p < e; p++) {
        int j = __ldg(&g_ecol[p]);
        float2 xv = __half22float2(__ldg(((const __half2*)(g_xh + (size_t)j * 64)) + lane));
        float2 sc = __ldg(&g_s2[j]);          // broadcast within warp
        a0x += xv.x;          a0y += xv.y;
        a1x += xv.x * sc.x;   a1y += xv.y * sc.x;
        a2x += xv.x * sc.y;   a2y += xv.y * sc.y;
    }
    float dr = 1.0f / deg[w];
    __half2* outh = (__half2*)(g_y1h + (size_t)w * F);
    outh[lane]      = __floats2half2_rn(a0x * dr, a0y * dr);
    outh[lane + 32] = __floats2half2_rn(a1x * dr, a1y * dr);
    outh[lane + 64] = __floats2half2_rn(a2x * dr, a2y * dr);
}

// ---------------------------------------------------------------------------
// K5: FUSED hop-2 SpMM + transposed output. Gathers fp16 y1 (38.4MB working
//     set, L2-resident). x3 blocks recomputed from fp32 x (exact).
//     out[n, d*9+k] = concat(x3|y1|y2)[n, k*64+d] via padded smem tile.
// ---------------------------------------------------------------------------
__global__ void spmm2_out_kernel(const float* __restrict__ x,
                                 const float* __restrict__ deg,
                                 float* __restrict__ out, int N) {
    __shared__ float tile[8 * 9 * 65];        // per-warp 585-float tile
    int wid = threadIdx.x >> 5, lane = threadIdx.x & 31;
    int n = blockIdx.x * 8 + wid;
    if (n >= N) return;
    float* t = tile + wid * 585;

    int s = g_rowptr[n], e = g_cursor[n];
    float a0x = 0.f, a0y = 0.f, a1x = 0.f, a1y = 0.f, a2x = 0.f, a2y = 0.f;
    #pragma unroll 4
    for (int p = s; p < e; p++) {
        int j = __ldg(&g_ecol[p]);
        const __half2* r = (const __half2*)(g_y1h + (size_t)j * F);
        float2 v0 = __half22float2(__ldg(r + lane));
        float2 v1 = __half22float2(__ldg(r + lane + 32));
        float2 v2 = __half22float2(__ldg(r + lane + 64));
        a0x += v0.x; a0y += v0.y;
        a1x += v1.x; a1y += v1.y;
        a2x += v2.x; a2y += v2.y;
    }

    float dr = 1.0f / deg[n];
    float2 sc = g_s2[n];
    float2 xv = __ldg(((const float2*)(x + (size_t)n * 64)) + lane);
    const __half2* yr = (const __half2*)(g_y1h + (size_t)n * F);
    float2 y0  = __half22float2(yr[lane]);
    float2 y1v = __half22float2(yr[lane + 32]);
    float2 y2v = __half22float2(yr[lane + 64]);

    int d0 = lane * 2;
    // k = 0..2 : x3 blocks (x, x*rsqrt(deg), x*sqrt(deg)) — exact fp32
    t[0 * 65 + d0] = xv.x;          t[0 * 65 + d0 + 1] = xv.y;
    t[1 * 65 + d0] = xv.x * sc.x;   t[1 * 65 + d0 + 1] = xv.y * sc.x;
    t[2 * 65 + d0] = xv.x * sc.y;   t[2 * 65 + d0 + 1] = xv.y * sc.y;
    // k = 3..5 : y1 blocks
    t[3 * 65 + d0] = y0.x;          t[3 * 65 + d0 + 1] = y0.y;
    t[4 * 65 + d0] = y1v.x;         t[4 * 65 + d0 + 1] = y1v.y;
    t[5 * 65 + d0] = y2v.x;         t[5 * 65 + d0 + 1] = y2v.y;
    // k = 6..8 : y2 = degrev*spmm(y1) - x3
    t[6 * 65 + d0] = a0x * dr - xv.x;          t[6 * 65 + d0 + 1] = a0y * dr - xv.y;
    t[7 * 65 + d0] = a1x * dr - xv.x * sc.x;   t[7 * 65 + d0 + 1] = a1y * dr - xv.y * sc.x;
    t[8 * 65 + d0] = a2x * dr - xv.x * sc.y;   t[8 * 65 + d0 + 1] = a2y * dr - xv.y * sc.y;
    __syncwarp();

    // coalesced store of the transposed row: out[n, d*9+k]
    float* o = out + (size_t)n * OUTC;
    #pragma unroll
    for (int i = 0; i < 18; i++) {
        int r = i * 32 + lane;
        int d = r / 9, k = r - d * 9;
        o[r] = t[k * 65 + d];
    }
}

// ---------------------------------------------------------------------------
extern "C" void kernel_launch(void* const* d_in, const int* in_sizes, int n_in,
                              void* d_out, int out_size) {
    const float* x   = (const float*)d_in[0];
    const float* deg = (const float*)d_in[1];
    const int*   row = (const int*)d_in[2];
    const int*   col = (const int*)d_in[3];
    float* out = (float*)d_out;

    int N = in_sizes[1];          // deg has N elements
    int E = in_sizes[2];          // row has E elements

    init_kernel<<<((size_t)N * 32 + 255) / 256, 256>>>(x, deg, N);
    scan_kernel<<<1, 1024>>>(deg, N);
    fill_kernel<<<(E + 255) / 256, 256>>>(row, col, E);
    spmm1_kernel<<<((size_t)N * 32 + 255) / 256, 256>>>(deg, N);
    spmm2_out_kernel<<<(N + 7) / 8, 256>>>(x, deg, out, N);
}

// round 7
// speedup vs baseline: 2.0778x; 1.2941x over previous
#include <cuda_runtime.h>
#include <cuda_bf16.h>
#include <cuda_fp16.h>
#include <cstdint>

// Problem constants (fixed by dataset): N=100000, D=64, E=1600000
#define NMAX 100000
#define EMAX 1600000
#define ESLOTS (EMAX + NMAX)   // rowptr built from deg upper-bounds counts
#define F    192               // 3*D features per hop stage
#define OUTC 576               // 9*64 output columns per node
#define SCAN_CHUNK 4096        // elems per scan block (1024 thr x 4)
#define MAXBLK 64

// ---- scratch (static device globals; no runtime allocation allowed) ----
__device__ __half g_xh [(size_t)NMAX * 64];  // x in fp16 (hop-1 gather)
__device__ __half g_y1h[(size_t)NMAX * F];   // hop-1 result, fp16
__device__ float2 g_s2[NMAX];                // (rsqrt(deg), sqrt(deg))
__device__ ulonglong2 g_s2p[NMAX];           // packed f32x2 {(r,r),(q,q)}
__device__ int   g_rowptr[NMAX + 1];
__device__ int   g_cursor[NMAX];             // fill cursor; after fill = row end
__device__ int   g_bsum[MAXBLK];             // scan block partials
__device__ int   g_boff[MAXBLK];             // scan block offsets
__device__ int   g_ecol[ESLOTS];             // CSR column indices

// ---- packed f32x2 helpers -------------------------------------------------
#define PACKF2(out, lo, hi) \
    asm("mov.b64 %0, {%1, %2};" : "=l"(out) : "r"(__float_as_uint(lo)), "r"(__float_as_uint(hi)))
#define UNPACKF2(lo, hi, in) \
    asm("mov.b64 {%0, %1}, %2;" : "=r"(lo), "=r"(hi) : "l"(in))
#define ADDF2(d, a, b) \
    asm("add.rn.f32x2 %0, %1, %2;" : "=l"(d) : "l"(a), "l"(b))
#define MULF2(d, a, b) \
    asm("mul.rn.f32x2 %0, %1, %2;" : "=l"(d) : "l"(a), "l"(b))
#define FMAF2(d, a, b, c) \
    asm("fma.rn.f32x2 %0, %1, %2, %3;" : "=l"(d) : "l"(a), "l"(b), "l"(c))

// ---------------------------------------------------------------------------
// K1: per-node scale factors (+packed form) + x -> fp16 conversion
// ---------------------------------------------------------------------------
__global__ void init_kernel(const float* __restrict__ x,
                            const float* __restrict__ deg, int N) {
    int t = blockIdx.x * blockDim.x + threadIdx.x;
    int total = N * 32;                 // N*64 floats as float2
    if (t < total) {
        float2 v = __ldg(((const float2*)x) + t);
        ((__half2*)g_xh)[t] = __floats2half2_rn(v.x, v.y);
    }
    if (t < N) {
        float d = __ldg(&deg[t]);
        float r = rsqrtf(d);
        float q = d * r;
        g_s2[t] = make_float2(r, q);
        unsigned int rb = __float_as_uint(r), qb = __float_as_uint(q);
        g_s2p[t] = make_ulonglong2(((unsigned long long)rb << 32) | rb,
                                   ((unsigned long long)qb << 32) | qb);
    }
}

// ---------------------------------------------------------------------------
// Parallel scan over (int)deg: A = per-block local exclusive scan + partial,
// B = scan of partials (1 warp), C = add offsets + init cursor.
// ---------------------------------------------------------------------------
__global__ void scanA_kernel(const float* __restrict__ deg, int N) {
    __shared__ int warp_sums[32];
    const int tid = threadIdx.x, lane = tid & 31, wid = tid >> 5;
    int idx = blockIdx.x * SCAN_CHUNK + tid * 4;

    int v0 = (idx     < N) ? (int)__ldg(&deg[idx])     : 0;
    int v1 = (idx + 1 < N) ? (int)__ldg(&deg[idx + 1]) : 0;
    int v2 = (idx + 2 < N) ? (int)__ldg(&deg[idx + 2]) : 0;
    int v3 = (idx + 3 < N) ? (int)__ldg(&deg[idx + 3]) : 0;
    int t = v0 + v1 + v2 + v3;

    int s = t;
    #pragma unroll
    for (int off = 1; off < 32; off <<= 1) {
        int u = __shfl_up_sync(0xFFFFFFFFu, s, off);
        if (lane >= off) s += u;
    }
    if (lane == 31) warp_sums[wid] = s;
    __syncthreads();
    if (wid == 0) {
        int ws = warp_sums[lane];
        int s2 = ws;
        #pragma unroll
        for (int off = 1; off < 32; off <<= 1) {
            int u = __shfl_up_sync(0xFFFFFFFFu, s2, off);
            if (lane >= off) s2 += u;
        }
        warp_sums[lane] = s2 - ws;
    }
    __syncthreads();
    int excl = warp_sums[wid] + (s - t);   // block-local exclusive prefix

    if (idx     < N) g_rowptr[idx]     = excl;
    if (idx + 1 < N) g_rowptr[idx + 1] = excl + v0;
    if (idx + 2 < N) g_rowptr[idx + 2] = excl + v0 + v1;
    if (idx + 3 < N) g_rowptr[idx + 3] = excl + v0 + v1 + v2;
    if (tid == 1023) g_bsum[blockIdx.x] = excl + t;   // block total
}

__global__ void scanB_kernel(int nblk) {
    int lane = threadIdx.x;
    int v = (lane < nblk) ? g_bsum[lane] : 0;
    int s = v;
    #pragma unroll
    for (int off = 1; off < 32; off <<= 1) {
        int u = __shfl_up_sync(0xFFFFFFFFu, s, off);
        if (lane >= off) s += u;
    }
    if (lane < nblk) g_boff[lane] = s - v;   // exclusive
}

__global__ void scanC_kernel(int N) {
    int off = __ldg(&g_boff[blockIdx.x]);
    int idx = blockIdx.x * SCAN_CHUNK + threadIdx.x * 4;
    #pragma unroll
    for (int k = 0; k < 4; k++) {
        if (idx + k < N) {
            int r = g_rowptr[idx + k] + off;
            g_rowptr[idx + k] = r;
            g_cursor[idx + k] = r;
        }
    }
}

// ---------------------------------------------------------------------------
// K3: scatter edges into CSR buckets, 4 edges/thread for MLP
// ---------------------------------------------------------------------------
__global__ void fill_kernel(const int* __restrict__ row, const int* __restrict__ col, int E) {
    int t = blockIdx.x * blockDim.x + threadIdx.x;
    int e = t * 4;
    if (e + 3 < E) {
        int4 r4 = __ldg((const int4*)(row + e));
        int4 c4 = __ldg((const int4*)(col + e));
        int p0 = atomicAdd(&g_cursor[r4.x], 1);
        int p1 = atomicAdd(&g_cursor[r4.y], 1);
        int p2 = atomicAdd(&g_cursor[r4.z], 1);
        int p3 = atomicAdd(&g_cursor[r4.w], 1);
        g_ecol[p0] = c4.x; g_ecol[p1] = c4.y;
        g_ecol[p2] = c4.z; g_ecol[p3] = c4.w;
    } else {
        for (; e < E; e++) {
            int p = atomicAdd(&g_cursor[row[e]], 1);
            g_ecol[p] = col[e];
        }
    }
}

// ---------------------------------------------------------------------------
// K4: hop-1 SpMM over fp16 x, packed-f32x2 math. Warp per node.
// ---------------------------------------------------------------------------
__global__ void spmm1_kernel(const float* __restrict__ deg, int N) {
    int w = (blockIdx.x * blockDim.x + threadIdx.x) >> 5;
    int lane = threadIdx.x & 31;
    if (w >= N) return;
    int s = g_rowptr[w], e = g_cursor[w];   // true end after fill

    unsigned long long a0 = 0ull, a1 = 0ull, a2 = 0ull;
    #pragma unroll 4
    for (int p = s; p < e; p++) {
        int j = __ldg(&g_ecol[p]);
        __half2 h = __ldg(((const __half2*)(g_xh + (size_t)j * 64)) + lane);
        ulonglong2 sp = __ldg(&g_s2p[j]);     // uniform LDG.128
        float lo = __low2float(h), hi = __high2float(h);
        unsigned long long xv;
        PACKF2(xv, lo, hi);
        ADDF2(a0, a0, xv);
        FMAF2(a1, xv, sp.x, a1);
        FMAF2(a2, xv, sp.y, a2);
    }
    float dr = 1.0f / deg[w];
    unsigned long long drp;
    PACKF2(drp, dr, dr);
    MULF2(a0, a0, drp);
    MULF2(a1, a1, drp);
    MULF2(a2, a2, drp);
    unsigned int l0, h0, l1, h1, l2, h2;
    UNPACKF2(l0, h0, a0); UNPACKF2(l1, h1, a1); UNPACKF2(l2, h2, a2);
    __half2* outh = (__half2*)(g_y1h + (size_t)w * F);
    outh[lane]      = __floats2half2_rn(__uint_as_float(l0), __uint_as_float(h0));
    outh[lane + 32] = __floats2half2_rn(__uint_as_float(l1), __uint_as_float(h1));
    outh[lane + 64] = __floats2half2_rn(__uint_as_float(l2), __uint_as_float(h2));
}

// ---------------------------------------------------------------------------
// K5: FUSED hop-2 SpMM + transposed output. Pairwise __hadd2 pre-reduction
//     (one fp16 rounding on 2-term sums, then exact fp32 accumulation).
// ---------------------------------------------------------------------------
__global__ void spmm2_out_kernel(const float* __restrict__ x,
                                 const float* __restrict__ deg,
                                 float* __restrict__ out, int N) {
    __shared__ float tile[8 * 9 * 65];        // per-warp 585-float tile
    int wid = threadIdx.x >> 5, lane = threadIdx.x & 31;
    int n = blockIdx.x * 8 + wid;
    if (n >= N) return;
    float* t = tile + wid * 585;

    int s = g_rowptr[n], e = g_cursor[n];
    float a0x = 0.f, a0y = 0.f, a1x = 0.f, a1y = 0.f, a2x = 0.f, a2y = 0.f;
    int p = s;
    #pragma unroll 2
    for (; p + 1 < e; p += 2) {
        int j0 = __ldg(&g_ecol[p]);
        int j1 = __ldg(&g_ecol[p + 1]);
        const __half2* r0 = (const __half2*)(g_y1h + (size_t)j0 * F);
        const __half2* r1 = (const __half2*)(g_y1h + (size_t)j1 * F);
        __half2 w0 = __hadd2(__ldg(r0 + lane),      __ldg(r1 + lane));
        __half2 w1 = __hadd2(__ldg(r0 + lane + 32), __ldg(r1 + lane + 32));
        __half2 w2 = __hadd2(__ldg(r0 + lane + 64), __ldg(r1 + lane + 64));
        float2 f0 = __half22float2(w0);
        float2 f1 = __half22float2(w1);
        float2 f2 = __half22float2(w2);
        a0x += f0.x; a0y += f0.y;
        a1x += f1.x; a1y += f1.y;
        a2x += f2.x; a2y += f2.y;
    }
    if (p < e) {                               // odd tail
        int j = __ldg(&g_ecol[p]);
        const __half2* r = (const __half2*)(g_y1h + (size_t)j * F);
        float2 f0 = __half22float2(__ldg(r + lane));
        float2 f1 = __half22float2(__ldg(r + lane + 32));
        float2 f2 = __half22float2(__ldg(r + lane + 64));
        a0x += f0.x; a0y += f0.y;
        a1x += f1.x; a1y += f1.y;
        a2x += f2.x; a2y += f2.y;
    }

    float dr = 1.0f / deg[n];
    float2 sc = g_s2[n];
    float2 xv = __ldg(((const float2*)(x + (size_t)n * 64)) + lane);
    const __half2* yr = (const __half2*)(g_y1h + (size_t)n * F);
    float2 y0  = __half22float2(yr[lane]);
    float2 y1v = __half22float2(yr[lane + 32]);
    float2 y2v = __half22float2(yr[lane + 64]);

    int d0 = lane * 2;
    // k = 0..2 : x3 blocks (x, x*rsqrt(deg), x*sqrt(deg)) — exact fp32
    t[0 * 65 + d0] = xv.x;          t[0 * 65 + d0 + 1] = xv.y;
    t[1 * 65 + d0] = xv.x * sc.x;   t[1 * 65 + d0 + 1] = xv.y * sc.x;
    t[2 * 65 + d0] = xv.x * sc.y;   t[2 * 65 + d0 + 1] = xv.y * sc.y;
    // k = 3..5 : y1 blocks
    t[3 * 65 + d0] = y0.x;          t[3 * 65 + d0 + 1] = y0.y;
    t[4 * 65 + d0] = y1v.x;         t[4 * 65 + d0 + 1] = y1v.y;
    t[5 * 65 + d0] = y2v.x;         t[5 * 65 + d0 + 1] = y2v.y;
    // k = 6..8 : y2 = degrev*spmm(y1) - x3
    t[6 * 65 + d0] = a0x * dr - xv.x;          t[6 * 65 + d0 + 1] = a0y * dr - xv.y;
    t[7 * 65 + d0] = a1x * dr - xv.x * sc.x;   t[7 * 65 + d0 + 1] = a1y * dr - xv.y * sc.x;
    t[8 * 65 + d0] = a2x * dr - xv.x * sc.y;   t[8 * 65 + d0 + 1] = a2y * dr - xv.y * sc.y;
    __syncwarp();

    // coalesced store of the transposed row: out[n, d*9+k]
    float* o = out + (size_t)n * OUTC;
    #pragma unroll
    for (int i = 0; i < 18; i++) {
        int r = i * 32 + lane;
        int d = r / 9, k = r - d * 9;
        o[r] = t[k * 65 + d];
    }
}

// ---------------------------------------------------------------------------
extern "C" void kernel_launch(void* const* d_in, const int* in_sizes, int n_in,
                              void* d_out, int out_size) {
    const float* x   = (const float*)d_in[0];
    const float* deg = (const float*)d_in[1];
    const int*   row = (const int*)d_in[2];
    const int*   col = (const int*)d_in[3];
    float* out = (float*)d_out;

    int N = in_sizes[1];          // deg has N elements
    int E = in_sizes[2];          // row has E elements
    int nblk = (N + SCAN_CHUNK - 1) / SCAN_CHUNK;   // 25 for N=100000

    init_kernel<<<((size_t)N * 32 + 255) / 256, 256>>>(x, deg, N);
    scanA_kernel<<<nblk, 1024>>>(deg, N);
    scanB_kernel<<<1, 32>>>(nblk);
    scanC_kernel<<<nblk, 1024>>>(N);
    fill_kernel<<<(E / 4 + 255) / 256, 256>>>(row, col, E);
    spmm1_kernel<<<((size_t)N * 32 + 255) / 256, 256>>>(deg, N);
    spmm2_out_kernel<<<(N + 7) / 8, 256>>>(x, deg, out, N);
}

// round 9
// speedup vs baseline: 2.1764x; 1.0475x over previous
#include <cuda_runtime.h>
#include <cuda_bf16.h>
#include <cuda_fp16.h>
#include <cstdint>

// Problem constants (fixed by dataset): N=100000, D=64, E=1600000
#define NMAX 100000
#define EMAX 1600000
#define ESLOTS (EMAX + NMAX)   // rowptr built from deg upper-bounds counts
#define F    192               // 3*D features per hop stage
#define OUTC 576               // 9*64 output columns per node
#define SCAN_CHUNK 4096        // elems per scan block (1024 thr x 4)
#define MAXBLK 64

// ---- scratch (static device globals; no runtime allocation allowed) ----
__device__ __half  g_xh [(size_t)NMAX * 64];  // x in fp16 (hop-1 gather)
__device__ __half  g_y1h[(size_t)NMAX * F];   // hop-1 result, fp16
__device__ float2  g_s2[NMAX];                // (rsqrt(deg), sqrt(deg)) fp32
__device__ __half2 g_s2h[NMAX];               // (rsqrt(deg), sqrt(deg)) fp16
__device__ int   g_rowptr[NMAX + 1];
__device__ int   g_cursor[NMAX];             // fill cursor; after fill = row end
__device__ int   g_bsum[MAXBLK];             // scan block partials
__device__ int   g_boff[MAXBLK];             // scan block offsets
__device__ int   g_ecol[ESLOTS];             // CSR column indices

// ---------------------------------------------------------------------------
// K1: per-node scale factors (fp32 + fp16) + x -> fp16 conversion
// ---------------------------------------------------------------------------
__global__ void init_kernel(const float* __restrict__ x,
                            const float* __restrict__ deg, int N) {
    int t = blockIdx.x * blockDim.x + threadIdx.x;
    int total = N * 32;                 // N*64 floats as float2
    if (t < total) {
        float2 v = __ldg(((const float2*)x) + t);
        ((__half2*)g_xh)[t] = __floats2half2_rn(v.x, v.y);
    }
    if (t < N) {
        float d = __ldg(&deg[t]);
        float r = rsqrtf(d);
        float q = d * r;
        g_s2[t]  = make_float2(r, q);
        g_s2h[t] = __floats2half2_rn(r, q);
    }
}

// ---------------------------------------------------------------------------
// Parallel scan over (int)deg: A = per-block local scan, B = partials (1 warp),
// C = add offsets + init cursor.
// ---------------------------------------------------------------------------
__global__ void scanA_kernel(const float* __restrict__ deg, int N) {
    __shared__ int warp_sums[32];
    const int tid = threadIdx.x, lane = tid & 31, wid = tid >> 5;
    int idx = blockIdx.x * SCAN_CHUNK + tid * 4;

    int v0 = (idx     < N) ? (int)__ldg(&deg[idx])     : 0;
    int v1 = (idx + 1 < N) ? (int)__ldg(&deg[idx + 1]) : 0;
    int v2 = (idx + 2 < N) ? (int)__ldg(&deg[idx + 2]) : 0;
    int v3 = (idx + 3 < N) ? (int)__ldg(&deg[idx + 3]) : 0;
    int t = v0 + v1 + v2 + v3;

    int s = t;
    #pragma unroll
    for (int off = 1; off < 32; off <<= 1) {
        int u = __shfl_up_sync(0xFFFFFFFFu, s, off);
        if (lane >= off) s += u;
    }
    if (lane == 31) warp_sums[wid] = s;
    __syncthreads();
    if (wid == 0) {
        int ws = warp_sums[lane];
        int s2 = ws;
        #pragma unroll
        for (int off = 1; off < 32; off <<= 1) {
            int u = __shfl_up_sync(0xFFFFFFFFu, s2, off);
            if (lane >= off) s2 += u;
        }
        warp_sums[lane] = s2 - ws;
    }
    __syncthreads();
    int excl = warp_sums[wid] + (s - t);   // block-local exclusive prefix

    if (idx     < N) g_rowptr[idx]     = excl;
    if (idx + 1 < N) g_rowptr[idx + 1] = excl + v0;
    if (idx + 2 < N) g_rowptr[idx + 2] = excl + v0 + v1;
    if (idx + 3 < N) g_rowptr[idx + 3] = excl + v0 + v1 + v2;
    if (tid == 1023) g_bsum[blockIdx.x] = excl + t;   // block total
}

__global__ void scanB_kernel(int nblk) {
    int lane = threadIdx.x;
    int v = (lane < nblk) ? g_bsum[lane] : 0;
    int s = v;
    #pragma unroll
    for (int off = 1; off < 32; off <<= 1) {
        int u = __shfl_up_sync(0xFFFFFFFFu, s, off);
        if (lane >= off) s += u;
    }
    if (lane < nblk) g_boff[lane] = s - v;   // exclusive
}

__global__ void scanC_kernel(int N) {
    int off = __ldg(&g_boff[blockIdx.x]);
    int idx = blockIdx.x * SCAN_CHUNK + threadIdx.x * 4;
    #pragma unroll
    for (int k = 0; k < 4; k++) {
        if (idx + k < N) {
            int r = g_rowptr[idx + k] + off;
            g_rowptr[idx + k] = r;
            g_cursor[idx + k] = r;
        }
    }
}

// ---------------------------------------------------------------------------
// K3: scatter edges into CSR buckets, 4 edges/thread for MLP
// ---------------------------------------------------------------------------
__global__ void fill_kernel(const int* __restrict__ row, const int* __restrict__ col, int E) {
    int t = blockIdx.x * blockDim.x + threadIdx.x;
    int e = t * 4;
    if (e + 3 < E) {
        int4 r4 = __ldg((const int4*)(row + e));
        int4 c4 = __ldg((const int4*)(col + e));
        int p0 = atomicAdd(&g_cursor[r4.x], 1);
        int p1 = atomicAdd(&g_cursor[r4.y], 1);
        int p2 = atomicAdd(&g_cursor[r4.z], 1);
        int p3 = atomicAdd(&g_cursor[r4.w], 1);
        g_ecol[p0] = c4.x; g_ecol[p1] = c4.y;
        g_ecol[p2] = c4.z; g_ecol[p3] = c4.w;
    } else {
        for (; e < E; e++) {
            int p = atomicAdd(&g_cursor[row[e]], 1);
            g_ecol[p] = col[e];
        }
    }
}

// ---------------------------------------------------------------------------
// K4: hop-1 SpMM, fp16 HFMA2 accumulation. Warp per node; lane l owns half2
//     column l of each of the 3 feature groups (offsets 0/32/64 half2 units).
// ---------------------------------------------------------------------------
__global__ void spmm1_kernel(const float* __restrict__ deg, int N) {
    int w = (blockIdx.x * blockDim.x + threadIdx.x) >> 5;
    int lane = threadIdx.x & 31;
    if (w >= N) return;
    int s = g_rowptr[w], e = g_cursor[w];   // true end after fill

    __half2 a0 = __float2half2_rn(0.f);
    __half2 a1 = a0, a2 = a0;
    #pragma unroll 4
    for (int p = s; p < e; p++) {
        int j = __ldg(&g_ecol[p]);
        __half2 xv = __ldg(((const __half2*)(g_xh + (size_t)j * 64)) + lane);
        __half2 sh = __ldg(&g_s2h[j]);        // uniform broadcast
        __half2 rr = __low2half2(sh);
        __half2 qq = __high2half2(sh);
        a0 = __hadd2(a0, xv);
        a1 = __hfma2(xv, rr, a1);
        a2 = __hfma2(xv, qq, a2);
    }
    float dr = 1.0f / deg[w];
    float2 f0 = __half22float2(a0);
    float2 f1 = __half22float2(a1);
    float2 f2 = __half22float2(a2);
    __half2* outh = (__half2*)(g_y1h + (size_t)w * F);
    outh[lane]      = __floats2half2_rn(f0.x * dr, f0.y * dr);
    outh[lane + 32] = __floats2half2_rn(f1.x * dr, f1.y * dr);
    outh[lane + 64] = __floats2half2_rn(f2.x * dr, f2.y * dr);
}

// ---------------------------------------------------------------------------
// K5: FUSED hop-2 SpMM + transposed output.
//     Gather: lane l<24 loads uint4 (16B) chunk l of the 384B y1 row ->
//     ONE LDG.128 + 4 HADD2 per edge. Lane l owns group k=l>>3, cols
//     d0..d0+7 with d0=(l&7)*8. Epilogue rebuilds x3 (fp32 exact) and y1,
//     writes the 9x64 padded smem tile, then stores transposed.
// ---------------------------------------------------------------------------
__global__ void spmm2_out_kernel(const float* __restrict__ x,
                                 const float* __restrict__ deg,
                                 float* __restrict__ out, int N) {
    __shared__ float tile[8 * 9 * 65];        // per-warp 585-float tile
    int wid = threadIdx.x >> 5, lane = threadIdx.x & 31;
    int n = blockIdx.x * 8 + wid;
    if (n >= N) return;
    float* t = tile + wid * 585;
    bool act = lane < 24;

    int s = g_rowptr[n], e = g_cursor[n];
    __half2 acc0 = __float2half2_rn(0.f);
    __half2 acc1 = acc0, acc2 = acc0, acc3 = acc0;
    #pragma unroll 4
    for (int p = s; p < e; p++) {
        int j = __ldg(&g_ecol[p]);
        if (act) {
            uint4 v = __ldg(((const uint4*)(g_y1h + (size_t)j * F)) + lane);
            acc0 = __hadd2(acc0, *(__half2*)&v.x);
            acc1 = __hadd2(acc1, *(__half2*)&v.y);
            acc2 = __hadd2(acc2, *(__half2*)&v.z);
            acc3 = __hadd2(acc3, *(__half2*)&v.w);
        }
    }

    float dr = 1.0f / deg[n];
    float2 sc = g_s2[n];
    if (act) {
        int k = lane >> 3, d0 = (lane & 7) * 8;
        float f = (k == 0) ? 1.0f : ((k == 1) ? sc.x : sc.y);

        // own x slice (exact fp32): 8 floats
        const float* xr = x + (size_t)n * 64 + d0;
        float4 xa = __ldg((const float4*)xr);
        float4 xb = __ldg((const float4*)(xr + 4));

        // own y1 slice (same uint4 mapping)
        uint4 yv = __ldg(((const uint4*)(g_y1h + (size_t)n * F)) + lane);
        float2 y0 = __half22float2(*(__half2*)&yv.x);
        float2 y1 = __half22float2(*(__half2*)&yv.y);
        float2 y2 = __half22float2(*(__half2*)&yv.z);
        float2 y3 = __half22float2(*(__half2*)&yv.w);

        float2 a0 = __half22float2(acc0);
        float2 a1 = __half22float2(acc1);
        float2 a2 = __half22float2(acc2);
        float2 a3 = __half22float2(acc3);

        float x0 = xa.x * f, x1 = xa.y * f, x2 = xa.z * f, x3v = xa.w * f;
        float x4 = xb.x * f, x5 = xb.y * f, x6 = xb.z * f, x7 = xb.w * f;

        float* tk = t + k * 65 + d0;               // x3 block
        tk[0] = x0; tk[1] = x1; tk[2] = x2; tk[3] = x3v;
        tk[4] = x4; tk[5] = x5; tk[6] = x6; tk[7] = x7;

        float* t3 = t + (k + 3) * 65 + d0;         // y1 block
        t3[0] = y0.x; t3[1] = y0.y; t3[2] = y1.x; t3[3] = y1.y;
        t3[4] = y2.x; t3[5] = y2.y; t3[6] = y3.x; t3[7] = y3.y;

        float* t6 = t + (k + 6) * 65 + d0;         // y2 = dr*sum - x3
        t6[0] = a0.x * dr - x0; t6[1] = a0.y * dr - x1;
        t6[2] = a1.x * dr - x2; t6[3] = a1.y * dr - x3v;
        t6[4] = a2.x * dr - x4; t6[5] = a2.y * dr - x5;
        t6[6] = a3.x * dr - x6; t6[7] = a3.y * dr - x7;
    }
    __syncwarp();

    // coalesced store of the transposed row: out[n, d*9+k]
    float* o = out + (size_t)n * OUTC;
    #pragma unroll
    for (int i = 0; i < 18; i++) {
        int r = i * 32 + lane;
        int d = r / 9, k = r - d * 9;
        o[r] = t[k * 65 + d];
    }
}

// ---------------------------------------------------------------------------
extern "C" void kernel_launch(void* const* d_in, const int* in_sizes, int n_in,
                              void* d_out, int out_size) {
    const float* x   = (const float*)d_in[0];
    const float* deg = (const float*)d_in[1];
    const int*   row = (const int*)d_in[2];
    const int*   col = (const int*)d_in[3];
    float* out = (float*)d_out;

    int N = in_sizes[1];          // deg has N elements
    int E = in_sizes[2];          // row has E elements
    int nblk = (N + SCAN_CHUNK - 1) / SCAN_CHUNK;   // 25 for N=100000

    init_kernel<<<((size_t)N * 32 + 255) / 256, 256>>>(x, deg, N);
    scanA_kernel<<<nblk, 1024>>>(deg, N);
    scanB_kernel<<<1, 32>>>(nblk);
    scanC_kernel<<<nblk, 1024>>>(N);
    fill_kernel<<<(E / 4 + 255) / 256, 256>>>(row, col, E);
    spmm1_kernel<<<((size_t)N * 32 + 255) / 256, 256>>>(deg, N);
    spmm2_out_kernel<<<(N + 7) / 8, 256>>>(x, deg, out, N);
}